// round 16
// baseline (speedup 1.0000x reference)
#include <cuda_runtime.h>
#include <cstdint>

// Problem constants (shapes fixed by setup_inputs)
#define NC   19
#define HW   (512 * 1024)          // 524288
#define NB   16
#define NPIX (NB * HW)             // 8388608
#define HW4  (HW / 4)              // 131072 = 2^17
#define NP4  (NPIX / 4)            // 2097152
#define BINS (NC * NC)             // 361
#define WEIGHT 0.5
#define SMOOTH 1e-6
#define GRID 592                   // 148 SMs * 4 resident blocks = 1 full wave
#define TPB  256

// Global scratch (zero-initialized; each launch leaves it zeroed again)
__device__ unsigned int g_cm[BINS];
__device__ unsigned int g_done;

__global__ __launch_bounds__(TPB, 4)   // pins regs <= 64 -> 4 blocks/SM guaranteed
void sensspec_fused_kernel(const float* __restrict__ logits,
                           const int* __restrict__ target,
                           float* __restrict__ out) {
    __shared__ unsigned int sh[BINS];
    for (int i = threadIdx.x; i < BINS; i += TPB) sh[i] = 0u;
    __syncthreads();

    // ---- phase 1: argmax + block-local histogram (ceiling pattern) ----
    const int stride = GRID * TPB;
    for (int i4 = blockIdx.x * TPB + threadIdx.x; i4 < NP4; i4 += stride) {
        int b   = i4 >> 17;            // batch (HW4 = 2^17)
        int rem = i4 - (b << 17);
        const float4* base =
            reinterpret_cast<const float4*>(logits + (size_t)b * NC * HW) + rem;

        float4 m = base[0];            // default-cached LDG.128 (L1+L2)
        int ix = 0, iy = 0, iz = 0, iw = 0;
        #pragma unroll
        for (int c = 1; c < NC; c++) {
            float4 v = base[(size_t)c * HW4];
            if (v.x > m.x) { m.x = v.x; ix = c; }
            if (v.y > m.y) { m.y = v.y; iy = c; }
            if (v.z > m.z) { m.z = v.z; iz = c; }
            if (v.w > m.w) { m.w = v.w; iw = c; }
        }

        // target is int32 (JAX x64 disabled => int64 request yields int32)
        int4 t = reinterpret_cast<const int4*>(target)[i4];

        atomicAdd(&sh[t.x * NC + ix], 1u);
        atomicAdd(&sh[t.y * NC + iy], 1u);
        atomicAdd(&sh[t.z * NC + iz], 1u);
        atomicAdd(&sh[t.w * NC + iw], 1u);
    }

    __syncthreads();
    for (int i = threadIdx.x; i < BINS; i += TPB) {
        unsigned int v = sh[i];
        if (v) atomicAdd(&g_cm[i], v);
    }

    // ---- phase 2: last block finalizes ----
    __threadfence();
    __shared__ bool is_last;
    if (threadIdx.x == 0) {
        unsigned int n = atomicAdd(&g_done, 1u);
        is_last = (n == GRID - 1);
    }
    __syncthreads();
    if (!is_last) return;

    __threadfence();  // ensure all blocks' g_cm atomics are visible

    if (threadIdx.x < 32) {
        int lane = threadIdx.x;
        double acc = 0.0;
        if (lane < NC) {
            double rowsum = 0.0, colsum = 0.0;
            #pragma unroll
            for (int j = 0; j < NC; j++) {
                rowsum += (double)g_cm[lane * NC + j];   // axis=1 (pred)
                colsum += (double)g_cm[j * NC + lane];   // axis=0 (true)
            }
            double tp = (double)g_cm[lane * NC + lane];
            double fp = rowsum - tp;
            double fn = colsum - tp;
            double tn = (double)NPIX - tp - fp - fn;     // sum(CM) is exact
            double sens = (tp + SMOOTH) / (tp + fn + SMOOTH);
            double spec = (tn + SMOOTH) / (tn + fp + SMOOTH);
            acc = WEIGHT * sens + (1.0 - WEIGHT) * spec;
        }
        #pragma unroll
        for (int off = 16; off > 0; off >>= 1)
            acc += __shfl_down_sync(0xFFFFFFFFu, acc, off);
        if (lane == 0)
            out[0] = (float)(1.0 - acc / (double)NC);
    }
    __syncthreads();

    // reset globals so the next graph replay starts clean (deterministic)
    for (int i = threadIdx.x; i < BINS; i += TPB) g_cm[i] = 0u;
    if (threadIdx.x == 0) g_done = 0u;
}

extern "C" void kernel_launch(void* const* d_in, const int* in_sizes, int n_in,
                              void* d_out, int out_size) {
    const float* logits = (const float*)d_in[0];
    const int*   target = (const int*)d_in[1];
    float* out = (float*)d_out;

    sensspec_fused_kernel<<<GRID, TPB>>>(logits, target, out);
}

// round 17
// speedup vs baseline: 1.0190x; 1.0190x over previous
#include <cuda_runtime.h>
#include <cstdint>

// Problem constants (shapes fixed by setup_inputs)
#define NC   19
#define HW   (512 * 1024)          // 524288
#define NB   16
#define NPIX (NB * HW)             // 8388608
#define HW4  (HW / 4)              // 131072 = 2^17
#define NP4  (NPIX / 4)            // 2097152
#define BINS (NC * NC)             // 361
#define WEIGHT 0.5
#define SMOOTH 1e-6
#define GRID 592                   // 148 SMs * 4 resident blocks = 1 full wave
#define TPB  256

// Global scratch (zero-initialized; each launch leaves it zeroed again)
__device__ unsigned int g_cm[BINS];
__device__ unsigned int g_done;

__global__ __launch_bounds__(TPB, 4)   // pins regs <= 64 -> 4 blocks/SM guaranteed
void sensspec_fused_kernel(const float* __restrict__ logits,
                           const int* __restrict__ target,
                           float* __restrict__ out) {
    __shared__ unsigned int sh[BINS];
    for (int i = threadIdx.x; i < BINS; i += TPB) sh[i] = 0u;
    __syncthreads();

    // ---- phase 1: argmax + block-local histogram (ceiling pattern) ----
    const int stride = GRID * TPB;
    for (int i4 = blockIdx.x * TPB + threadIdx.x; i4 < NP4; i4 += stride) {
        int b   = i4 >> 17;            // batch (HW4 = 2^17)
        int rem = i4 - (b << 17);
        const float4* base =
            reinterpret_cast<const float4*>(logits + (size_t)b * NC * HW) + rem;

        float4 m = __ldcg(base);
        int ix = 0, iy = 0, iz = 0, iw = 0;
        #pragma unroll
        for (int c = 1; c < NC; c++) {
            float4 v = __ldcg(base + (size_t)c * HW4);
            if (v.x > m.x) { m.x = v.x; ix = c; }
            if (v.y > m.y) { m.y = v.y; iy = c; }
            if (v.z > m.z) { m.z = v.z; iz = c; }
            if (v.w > m.w) { m.w = v.w; iw = c; }
        }

        // target is int32 (JAX x64 disabled => int64 request yields int32)
        int4 t = __ldcg(reinterpret_cast<const int4*>(target) + i4);

        atomicAdd(&sh[t.x * NC + ix], 1u);
        atomicAdd(&sh[t.y * NC + iy], 1u);
        atomicAdd(&sh[t.z * NC + iz], 1u);
        atomicAdd(&sh[t.w * NC + iw], 1u);
    }

    __syncthreads();
    for (int i = threadIdx.x; i < BINS; i += TPB) {
        unsigned int v = sh[i];
        if (v) atomicAdd(&g_cm[i], v);
    }

    // ---- phase 2: last block finalizes ----
    __threadfence();
    __shared__ bool is_last;
    if (threadIdx.x == 0) {
        unsigned int n = atomicAdd(&g_done, 1u);
        is_last = (n == GRID - 1);
    }
    __syncthreads();
    if (!is_last) return;

    __threadfence();  // ensure all blocks' g_cm atomics are visible

    if (threadIdx.x < 32) {
        int lane = threadIdx.x;
        double acc = 0.0;
        if (lane < NC) {
            double rowsum = 0.0, colsum = 0.0;
            #pragma unroll
            for (int j = 0; j < NC; j++) {
                rowsum += (double)g_cm[lane * NC + j];   // axis=1 (pred)
                colsum += (double)g_cm[j * NC + lane];   // axis=0 (true)
            }
            double tp = (double)g_cm[lane * NC + lane];
            double fp = rowsum - tp;
            double fn = colsum - tp;
            double tn = (double)NPIX - tp - fp - fn;     // sum(CM) is exact
            double sens = (tp + SMOOTH) / (tp + fn + SMOOTH);
            double spec = (tn + SMOOTH) / (tn + fp + SMOOTH);
            acc = WEIGHT * sens + (1.0 - WEIGHT) * spec;
        }
        #pragma unroll
        for (int off = 16; off > 0; off >>= 1)
            acc += __shfl_down_sync(0xFFFFFFFFu, acc, off);
        if (lane == 0)
            out[0] = (float)(1.0 - acc / (double)NC);
    }
    __syncthreads();

    // reset globals so the next graph replay starts clean (deterministic)
    for (int i = threadIdx.x; i < BINS; i += TPB) g_cm[i] = 0u;
    if (threadIdx.x == 0) g_done = 0u;
}

extern "C" void kernel_launch(void* const* d_in, const int* in_sizes, int n_in,
                              void* d_out, int out_size) {
    const float* logits = (const float*)d_in[0];
    const int*   target = (const int*)d_in[1];
    float* out = (float*)d_out;

    sensspec_fused_kernel<<<GRID, TPB>>>(logits, target, out);
}